// round 6
// baseline (speedup 1.0000x reference)
#include <cuda_runtime.h>

// Problem constants (B=64, D=256, H=32, W=32, K=1024)
#define TOK_N   65536   // B*H*W tokens
#define DDIM    256
#define KCODES  1024

// Tiling
#define BM      64      // tokens per block
#define BN      128     // codes per tile
#define BD      32      // d-chunk staged in smem
#define TM      4       // tokens per thread
#define TN      8       // codes per thread (4 packed pairs)
#define NTHREADS 256    // 16 x 16

#define SMEM_FLOATS (DDIM*BM + BD*BN)     // 16384 + 4096 = 20480
#define SMEM_BYTES  (SMEM_FLOATS * 4)     // 81920

// Scratch in device globals (no allocations allowed in kernel_launch)
__device__ float g_cbT[DDIM * KCODES];      // transposed codebook [d][k]
__device__ float g_cnorm_half[KCODES];      // 0.5 * ||c_k||^2

// ---------------------------------------------------------------------------
// packed f32x2 FMA (sm_100+): d.lo = a.lo*b.lo + c.lo ; d.hi = a.hi*b.hi + c.hi
// ---------------------------------------------------------------------------
__device__ __forceinline__ float2 ffma2(float2 a, float2 b, float2 c) {
    unsigned long long ua = *reinterpret_cast<unsigned long long*>(&a);
    unsigned long long ub = *reinterpret_cast<unsigned long long*>(&b);
    unsigned long long uc = *reinterpret_cast<unsigned long long*>(&c);
    unsigned long long ud;
    asm("fma.rn.f32x2 %0, %1, %2, %3;" : "=l"(ud) : "l"(ua), "l"(ub), "l"(uc));
    float2 d;
    *reinterpret_cast<unsigned long long*>(&d) = ud;
    return d;
}

// ---------------------------------------------------------------------------
// Prep: transpose codebook to [D][K] and compute 0.5*||c||^2 per code.
// 1024 blocks x 256 threads, block k handles code k.
// ---------------------------------------------------------------------------
__global__ void __launch_bounds__(256) vq_prep(const float* __restrict__ cb) {
    int k = blockIdx.x;
    int d = threadIdx.x;
    float v = cb[k * DDIM + d];
    g_cbT[d * KCODES + k] = v;

    __shared__ float red[256];
    red[d] = v * v;
    __syncthreads();
    #pragma unroll
    for (int s = 128; s > 0; s >>= 1) {
        if (d < s) red[d] += red[d + s];
        __syncthreads();
    }
    if (d == 0) g_cnorm_half[k] = 0.5f * red[0];
}

// ---------------------------------------------------------------------------
// Main: per block, 64 tokens vs all 1024 codes.
//   score_k = dot(x, c_k) - 0.5*||c_k||^2 ;  argmax score == argmin distance.
//   x slab [64 tokens][256 d] staged once in smem (128-token runs of hw are
//   contiguous for fixed b, d — coalesced).
//   Epilogue: out[n*256+d] = cb[idx[n]][d], written to both z_hat and z_q.
// ---------------------------------------------------------------------------
__global__ void __launch_bounds__(NTHREADS, 2)
vq_main(const float* __restrict__ x,
        const float* __restrict__ cb,
        float* __restrict__ out,
        int halfElems) {
    extern __shared__ float smem[];
    float* xs = smem;                 // [DDIM][BM]  64 KB
    float* cs = smem + DDIM * BM;     // [BD][BN]    16 KB (reused for reduce)

    const int tid = threadIdx.x;
    const int tx = tid & 15;          // code group
    const int ty = tid >> 4;          // token group

    const int m0  = blockIdx.x * BM;  // first flat token (NHWC order)
    const int b   = m0 >> 10;         // 1024 hw positions per batch image
    const int hw0 = m0 & 1023;
    const float* xbase = x + (long long)b * (DDIM * 1024) + hw0;

    // Stage x slab: xs[d][m], m contiguous -> coalesced float4 loads
    #pragma unroll
    for (int f = tid; f < DDIM * BM / 4; f += NTHREADS) {
        int d  = f >> 4;              // BM/4 = 16 float4 per d-row
        int m4 = f & 15;
        float4 v = *reinterpret_cast<const float4*>(xbase + d * 1024 + m4 * 4);
        *reinterpret_cast<float4*>(&xs[d * BM + m4 * 4]) = v;
    }

    float bestv[TM];
    int   besti[TM];
    #pragma unroll
    for (int i = 0; i < TM; i++) { bestv[i] = -1e30f; besti[i] = 0; }

    for (int t = 0; t < KCODES / BN; ++t) {
        const int n0 = t * BN;
        float2 acc[TM][TN / 2];
        #pragma unroll
        for (int i = 0; i < TM; i++)
            #pragma unroll
            for (int jp = 0; jp < TN / 2; jp++)
                acc[i][jp] = make_float2(0.f, 0.f);

        for (int d0 = 0; d0 < DDIM; d0 += BD) {
            __syncthreads();   // cs reuse guard (also orders first xs use)
            // Stage codebook chunk cs[dd][n] from pre-transposed cbT (coalesced)
            #pragma unroll
            for (int f = tid; f < BD * BN / 4; f += NTHREADS) {
                int dd = f >> 5;      // BN/4 = 32 float4 per row
                int n4 = f & 31;
                *reinterpret_cast<float4*>(&cs[dd * BN + n4 * 4]) =
                    *reinterpret_cast<const float4*>(&g_cbT[(d0 + dd) * KCODES + n0 + n4 * 4]);
            }
            __syncthreads();

            #pragma unroll
            for (int dd = 0; dd < BD; ++dd) {
                float4 av  = *reinterpret_cast<const float4*>(&xs[(d0 + dd) * BM + ty * TM]);
                float4 bv0 = *reinterpret_cast<const float4*>(&cs[dd * BN + tx * TN]);
                float4 bv1 = *reinterpret_cast<const float4*>(&cs[dd * BN + tx * TN + 4]);
                float2 bp[4] = { make_float2(bv0.x, bv0.y), make_float2(bv0.z, bv0.w),
                                 make_float2(bv1.x, bv1.y), make_float2(bv1.z, bv1.w) };
                float a_[4] = { av.x, av.y, av.z, av.w };
                #pragma unroll
                for (int i = 0; i < TM; i++) {
                    float2 pa = make_float2(a_[i], a_[i]);
                    #pragma unroll
                    for (int jp = 0; jp < 4; jp++)
                        acc[i][jp] = ffma2(pa, bp[jp], acc[i][jp]);
                }
            }
        }

        // Tile epilogue: fold in -0.5||c||^2, running argmax (strict '>' keeps
        // the first max in ascending code order within this thread's slots).
        #pragma unroll
        for (int jp = 0; jp < 4; jp++) {
            int n = n0 + tx * TN + jp * 2;
            float c0 = g_cnorm_half[n];
            float c1 = g_cnorm_half[n + 1];
            #pragma unroll
            for (int i = 0; i < TM; i++) {
                float s0 = acc[i][jp].x - c0;
                float s1 = acc[i][jp].y - c1;
                if (s0 > bestv[i]) { bestv[i] = s0; besti[i] = n; }
                if (s1 > bestv[i]) { bestv[i] = s1; besti[i] = n + 1; }
            }
        }
    }

    // Cross-thread argmax reduce over the 16 tx lanes (index tie-break -> first-min)
    __syncthreads();
    float* rv = cs;                              // [BM][16]
    int*   ri = reinterpret_cast<int*>(cs + BM * 16);
    #pragma unroll
    for (int i = 0; i < TM; i++) {
        int m = ty * TM + i;
        rv[m * 16 + tx] = bestv[i];
        ri[m * 16 + tx] = besti[i];
    }
    __syncthreads();
    int* fidx = reinterpret_cast<int*>(cs + 2 * BM * 16);
    if (tid < BM) {
        float bv = rv[tid * 16];
        int   bi = ri[tid * 16];
        #pragma unroll
        for (int s = 1; s < 16; s++) {
            float v  = rv[tid * 16 + s];
            int   ix = ri[tid * 16 + s];
            if (v > bv || (v == bv && ix < bi)) { bv = v; bi = ix; }
        }
        fidx[tid] = bi;
    }
    __syncthreads();

    // Gather + write both outputs. Raw reshape => out linear index = n*D + d.
    const float4* cb4 = reinterpret_cast<const float4*>(cb);
    float4* o1 = reinterpret_cast<float4*>(out);
    float4* o2 = reinterpret_cast<float4*>(out + halfElems);
    #pragma unroll
    for (int f = tid; f < BM * (DDIM / 4); f += NTHREADS) {
        int m  = f >> 6;              // DDIM/4 = 64 float4 per token
        int d4 = f & 63;
        float4 v = cb4[fidx[m] * (DDIM / 4) + d4];
        long long o = (long long)(m0 + m) * (DDIM / 4) + d4;
        o1[o] = v;
        o2[o] = v;
    }
}

// ---------------------------------------------------------------------------
extern "C" void kernel_launch(void* const* d_in, const int* in_sizes, int n_in,
                              void* d_out, int out_size) {
    const float* x  = reinterpret_cast<const float*>(d_in[0]);
    const float* cb = reinterpret_cast<const float*>(d_in[1]);
    // Defensive: x has 16,777,216 elems, codebook 262,144 — disambiguate by size.
    if (n_in >= 2 && in_sizes[0] == KCODES * DDIM && in_sizes[1] != KCODES * DDIM) {
        const float* tmp = x; x = cb; cb = tmp;
    }
    float* out = reinterpret_cast<float*>(d_out);
    int halfElems = out_size / 2;     // (z_hat, z_q) concatenated; identical forward

    cudaFuncSetAttribute(vq_main, cudaFuncAttributeMaxDynamicSharedMemorySize, SMEM_BYTES);

    vq_prep<<<KCODES, 256>>>(cb);
    vq_main<<<TOK_N / BM, NTHREADS, SMEM_BYTES>>>(x, cb, out, halfElems);
}